// round 3
// baseline (speedup 1.0000x reference)
#include <cuda_runtime.h>
#include <math.h>

#define NMESH 131072
#define NPIV  256
#define FDIM  3
#define EDIM  64
#define BATCH 32
#define NPART 512   // KNN1 partial blocks (mesh chunks of 256)

// ---- scratch (no allocation allowed) ----
__device__ float g_pd2 [NPART*NPIV*3];
__device__ int   g_pidx[NPART*NPIV*3];
__device__ int   g_idx1[NPIV*3];
__device__ float g_c1  [NPIV*3];
__device__ float g_q   [BATCH*NPIV*EDIM];
__device__ float g_Q   [BATCH*NPIV*EDIM];
__device__ float g_K   [BATCH*NPIV*EDIM];
__device__ float g_y   [BATCH*NPIV*FDIM];   // [b][p][f]
__device__ float g_y2T [NPIV*BATCH*FDIM];   // [p][b][f]

// exact sorted-3 insert with index payload
__device__ __forceinline__ void ins3(float d, int i,
                                     float& d0, int& i0,
                                     float& d1, int& i1,
                                     float& d2, int& i2) {
    bool l2 = d < d2, l1 = d < d1, l0 = d < d0;
    float nd2 = l1 ? d1 : (l2 ? d : d2);  int ni2 = l1 ? i1 : (l2 ? i : i2);
    float nd1 = l0 ? d0 : (l1 ? d : d1);  int ni1 = l0 ? i0 : (l1 ? i : i1);
    float nd0 = l0 ? d  : d0;             int ni0 = l0 ? i  : i0;
    d0 = nd0; i0 = ni0; d1 = nd1; i1 = ni1; d2 = nd2; i2 = ni2;
}

// ============ K1a: partial KNN mesh->pivotal (per 256-node mesh chunk) ============
__global__ void k1a(const float2* __restrict__ meshp, const float2* __restrict__ pivp) {
    __shared__ float2 sp[256];
    int t = threadIdx.x, blk = blockIdx.x;
    sp[t] = meshp[blk * 256 + t];
    float2 P = pivp[t];                 // thread = pivotal index
    __syncthreads();

    float b0 = 3e38f, b1 = 3e38f, b2 = 3e38f;
#pragma unroll 8
    for (int c = 0; c < 256; c++) {
        float2 mp = sp[c];
        float dx = P.x - mp.x, dy = P.y - mp.y;
        float d2 = fmaf(dx, dx, dy * dy);
        float key = __uint_as_float((__float_as_uint(d2) & 0xFFFFFF00u) | (unsigned)c);
        float lo0 = fminf(key, b0), hi0 = fmaxf(key, b0);
        float lo1 = fminf(hi0, b1), hi1 = fmaxf(hi0, b1);
        b2 = fminf(hi1, b2); b0 = lo0; b1 = lo1;
    }
    float bb[3] = {b0, b1, b2};
    int base = blk * (NPIV * 3) + t * 3;
#pragma unroll
    for (int s = 0; s < 3; s++) {
        int li = (int)(__float_as_uint(bb[s]) & 0xFFu);
        float2 mp = sp[li];
        float dx = P.x - mp.x, dy = P.y - mp.y;
        g_pd2 [base + s] = fmaf(dx, dx, dy * dy);   // exact d2 for weights
        g_pidx[base + s] = blk * 256 + li;
    }
}

// ============ K1b: merge partials -> idx1, normalized weights c1 ============
__global__ void k1b() {
    int p = blockIdx.x, t = threadIdx.x;  // 128 threads
    float d0 = 3e38f, d1 = 3e38f, d2v = 3e38f;
    int   i0 = 0, i1 = 0, i2 = 0;
    for (int part = t; part < NPART; part += 128) {
        int base = part * (NPIV * 3) + p * 3;
#pragma unroll
        for (int s = 0; s < 3; s++)
            ins3(g_pd2[base + s], g_pidx[base + s], d0, i0, d1, i1, d2v, i2);
    }
    // warp tree-reduce (lane 0 ends valid)
    for (int off = 16; off; off >>= 1) {
        float a0 = __shfl_down_sync(~0u, d0, off);
        float a1 = __shfl_down_sync(~0u, d1, off);
        float a2 = __shfl_down_sync(~0u, d2v, off);
        int   j0 = __shfl_down_sync(~0u, i0, off);
        int   j1 = __shfl_down_sync(~0u, i1, off);
        int   j2 = __shfl_down_sync(~0u, i2, off);
        ins3(a0, j0, d0, i0, d1, i1, d2v, i2);
        ins3(a1, j1, d0, i0, d1, i1, d2v, i2);
        ins3(a2, j2, d0, i0, d1, i1, d2v, i2);
    }
    __shared__ float sd[4][3];
    __shared__ int   si[4][3];
    int w = t >> 5, l = t & 31;
    if (l == 0) {
        sd[w][0] = d0;  si[w][0] = i0;
        sd[w][1] = d1;  si[w][1] = i1;
        sd[w][2] = d2v; si[w][2] = i2;
    }
    __syncthreads();
    if (t == 0) {
        for (int w2 = 1; w2 < 4; w2++)
            for (int s = 0; s < 3; s++)
                ins3(sd[w2][s], si[w2][s], d0, i0, d1, i1, d2v, i2);
        float w0 = 1.f / fmaxf(d0, 1e-16f);
        float w1 = 1.f / fmaxf(d1, 1e-16f);
        float w2v = 1.f / fmaxf(d2v, 1e-16f);
        float inv = 1.f / (w0 + w1 + w2v);
        g_idx1[p * 3 + 0] = i0;  g_c1[p * 3 + 0] = w0 * inv;
        g_idx1[p * 3 + 1] = i1;  g_c1[p * 3 + 1] = w1 * inv;
        g_idx1[p * 3 + 2] = i2;  g_c1[p * 3 + 2] = w2v * inv;
    }
}

// ============ K2a: gather + LN + interp + feature/pos projection -> q, y ============
__global__ void k2a(const float* __restrict__ node_attr, const float* __restrict__ pivp,
                    const float* __restrict__ gamma, const float* __restrict__ beta,
                    const float* __restrict__ Wf, const float* __restrict__ bf,
                    const float* __restrict__ Wp, const float* __restrict__ bpv) {
    int e = threadIdx.x;                 // 64 lanes = E
    int bp_ = blockIdx.x;
    int b = bp_ >> 8, p = bp_ & 255;
    float y0 = 0.f, y1 = 0.f, y2 = 0.f;
    float g0 = gamma[0], g1 = gamma[1], g2 = gamma[2];
    float be0 = beta[0], be1 = beta[1], be2 = beta[2];
#pragma unroll
    for (int k = 0; k < 3; k++) {
        int n = g_idx1[p * 3 + k];
        float c = g_c1[p * 3 + k];
        const float* a = node_attr + (b * NMESH + n) * 3;
        float a0 = a[0], a1 = a[1], a2 = a[2];
        float mu = (a0 + a1 + a2) * (1.f / 3.f);
        float e0 = a0 - mu, e1 = a1 - mu, e2 = a2 - mu;
        float var = (e0 * e0 + e1 * e1 + e2 * e2) * (1.f / 3.f);
        float r = rsqrtf(var + 1e-5f);
        y0 = fmaf(c, fmaf(e0 * r, g0, be0), y0);
        y1 = fmaf(c, fmaf(e1 * r, g1, be1), y1);
        y2 = fmaf(c, fmaf(e2 * r, g2, be2), y2);
    }
    float px = pivp[p * 2], py = pivp[p * 2 + 1];
    float qv = bf[e] + y0 * Wf[e * 3] + y1 * Wf[e * 3 + 1] + y2 * Wf[e * 3 + 2]
             + bpv[e] + px * Wp[e * 2] + py * Wp[e * 2 + 1];
    int row = b * 256 + p;
    g_q[row * 64 + e] = qv;
    if (e == 0) {
        g_y[row * 3 + 0] = y0;
        g_y[row * 3 + 1] = y1;
        g_y[row * 3 + 2] = y2;
    }
}

// ============ K2b: Q/K projection GEMM: [8192x64] @ [64x64]^T (x2 via grid.y) ============
__global__ void k2b(const float* __restrict__ W, const float* __restrict__ bias) {
    __shared__ float qs[64][65];
    __shared__ float ws[64][65];
    int r0 = blockIdx.x * 64;
    int w0 = blockIdx.y * 64;
    int tid = threadIdx.x;
    for (int t = tid; t < 4096; t += 256) {
        int rr = t >> 6, cc = t & 63;
        qs[rr][cc] = g_q[(r0 + rr) * 64 + cc];
        ws[rr][cc] = W[(w0 + rr) * 64 + cc];
    }
    __syncthreads();
    int tr = tid >> 4, tc = tid & 15;
    float acc[4][4];
#pragma unroll
    for (int j = 0; j < 4; j++) {
        float bv = bias[w0 + tc * 4 + j];
#pragma unroll
        for (int i = 0; i < 4; i++) acc[i][j] = bv;
    }
#pragma unroll 8
    for (int e = 0; e < 64; e++) {
        float a[4], bb[4];
#pragma unroll
        for (int i = 0; i < 4; i++) a[i] = qs[tr * 4 + i][e];
#pragma unroll
        for (int j = 0; j < 4; j++) bb[j] = ws[tc * 4 + j][e];
#pragma unroll
        for (int i = 0; i < 4; i++)
#pragma unroll
            for (int j = 0; j < 4; j++) acc[i][j] = fmaf(a[i], bb[j], acc[i][j]);
    }
    float* outp = (blockIdx.y == 0) ? g_Q : g_K;
#pragma unroll
    for (int i = 0; i < 4; i++)
#pragma unroll
        for (int j = 0; j < 4; j++)
            outp[(r0 + tr * 4 + i) * 64 + tc * 4 + j] = acc[i][j];
}

// ============ K3: fused attention (scores -> softmax -> head-mean -> @ y) ============
__global__ void k3() {
    extern __shared__ float sm[];
    float* Ks = sm;              // 256*64
    float* ys = sm + 256 * 64;   // 256*3
    int b = blockIdx.x >> 3, ic = blockIdx.x & 7;
    int tid = threadIdx.x;       // 128 = 32 i x 4 h
    int il = tid >> 2, h = tid & 3;

    const float4* src = (const float4*)(g_K + b * 256 * 64);
    float4* dst = (float4*)Ks;
    for (int t = tid; t < 4096; t += 128) dst[t] = src[t];
    for (int t = tid; t < 768; t += 128) ys[t] = g_y[b * 768 + t];
    __syncthreads();

    int i = ic * 32 + il;
    float Qr[16];
    const float4* qp = (const float4*)(g_Q + (b * 256 + i) * 64 + h * 16);
#pragma unroll
    for (int d = 0; d < 4; d++) {
        float4 v = qp[d];
        Qr[4 * d + 0] = v.x; Qr[4 * d + 1] = v.y; Qr[4 * d + 2] = v.z; Qr[4 * d + 3] = v.w;
    }
    float l = 0.f, a0 = 0.f, a1 = 0.f, a2 = 0.f;
#pragma unroll 4
    for (int j = 0; j < 256; j++) {
        const float4* kr = (const float4*)(Ks + j * 64 + h * 16);
        float4 k0 = kr[0], k1 = kr[1], k2 = kr[2], k3v = kr[3];
        float s = 0.f;
        s = fmaf(Qr[0], k0.x, s);  s = fmaf(Qr[1], k0.y, s);
        s = fmaf(Qr[2], k0.z, s);  s = fmaf(Qr[3], k0.w, s);
        s = fmaf(Qr[4], k1.x, s);  s = fmaf(Qr[5], k1.y, s);
        s = fmaf(Qr[6], k1.z, s);  s = fmaf(Qr[7], k1.w, s);
        s = fmaf(Qr[8], k2.x, s);  s = fmaf(Qr[9], k2.y, s);
        s = fmaf(Qr[10], k2.z, s); s = fmaf(Qr[11], k2.w, s);
        s = fmaf(Qr[12], k3v.x, s); s = fmaf(Qr[13], k3v.y, s);
        s = fmaf(Qr[14], k3v.z, s); s = fmaf(Qr[15], k3v.w, s);
        float ev = __expf(fminf(s * 0.25f, 80.f));
        l += ev;
        a0 = fmaf(ev, ys[j * 3 + 0], a0);
        a1 = fmaf(ev, ys[j * 3 + 1], a1);
        a2 = fmaf(ev, ys[j * 3 + 2], a2);
    }
    float invl = 1.f / l;
    float r0 = a0 * invl, r1 = a1 * invl, r2 = a2 * invl;
    r0 += __shfl_xor_sync(~0u, r0, 1); r0 += __shfl_xor_sync(~0u, r0, 2);
    r1 += __shfl_xor_sync(~0u, r1, 1); r1 += __shfl_xor_sync(~0u, r1, 2);
    r2 += __shfl_xor_sync(~0u, r2, 1); r2 += __shfl_xor_sync(~0u, r2, 2);
    if (h == 0) {
        int o = (i * 32 + b) * 3;
        g_y2T[o + 0] = 0.25f * r0;
        g_y2T[o + 1] = 0.25f * r1;
        g_y2T[o + 2] = 0.25f * r2;
    }
}

// ============ K4: fused KNN pivotal->mesh + weighted scatter (writes 50MB out) ============
__global__ void k4(const float2* __restrict__ meshp, const float2* __restrict__ pivp,
                   float* __restrict__ out) {
    extern __shared__ float sm[];
    float* ysm = sm;                          // 256 rows x 97 (pad kills bank conflicts)
    float2* pp = (float2*)(sm + 256 * 97);    // byte offset 99328, 8B aligned
    int t = threadIdx.x;
    int m = blockIdx.x * 256 + t;
    pp[t] = pivp[t];
    {
        const float4* src = (const float4*)(g_y2T + t * 96);
        float* drow = ysm + t * 97;
#pragma unroll
        for (int c = 0; c < 24; c++) {
            float4 v = src[c];
            drow[c * 4 + 0] = v.x; drow[c * 4 + 1] = v.y;
            drow[c * 4 + 2] = v.z; drow[c * 4 + 3] = v.w;
        }
    }
    float2 MP = meshp[m];
    __syncthreads();

    float b0 = 3e38f, b1 = 3e38f, b2 = 3e38f;
#pragma unroll 8
    for (int c = 0; c < 256; c++) {
        float2 q = pp[c];
        float dx = MP.x - q.x, dy = MP.y - q.y;
        float d2 = fmaf(dx, dx, dy * dy);
        float key = __uint_as_float((__float_as_uint(d2) & 0xFFFFFF00u) | (unsigned)c);
        float lo0 = fminf(key, b0), hi0 = fmaxf(key, b0);
        float lo1 = fminf(hi0, b1), hi1 = fmaxf(hi0, b1);
        b2 = fminf(hi1, b2); b0 = lo0; b1 = lo1;
    }
    int i0 = (int)(__float_as_uint(b0) & 0xFFu);
    int i1 = (int)(__float_as_uint(b1) & 0xFFu);
    int i2 = (int)(__float_as_uint(b2) & 0xFFu);
    float w0, w1, w2;
    {
        float2 q = pp[i0];
        float dx = MP.x - q.x, dy = MP.y - q.y;
        w0 = 1.f / fmaxf(fmaf(dx, dx, dy * dy), 1e-16f);
    }
    {
        float2 q = pp[i1];
        float dx = MP.x - q.x, dy = MP.y - q.y;
        w1 = 1.f / fmaxf(fmaf(dx, dx, dy * dy), 1e-16f);
    }
    {
        float2 q = pp[i2];
        float dx = MP.x - q.x, dy = MP.y - q.y;
        w2 = 1.f / fmaxf(fmaf(dx, dx, dy * dy), 1e-16f);
    }
    float invden = 1.f / (w0 + w1 + w2);
    w0 *= invden; w1 *= invden; w2 *= invden;

    const float* r0p = ysm + i0 * 97;
    const float* r1p = ysm + i1 * 97;
    const float* r2p = ysm + i2 * 97;
#pragma unroll 4
    for (int b = 0; b < 32; b++) {
        int c = b * 3;
        float o0 = fmaf(w2, r2p[c + 0], fmaf(w1, r1p[c + 0], w0 * r0p[c + 0]));
        float o1 = fmaf(w2, r2p[c + 1], fmaf(w1, r1p[c + 1], w0 * r0p[c + 1]));
        float o2 = fmaf(w2, r2p[c + 2], fmaf(w1, r1p[c + 2], w0 * r0p[c + 2]));
        int ob = (b * NMESH + m) * 3;
        out[ob + 0] = o0; out[ob + 1] = o1; out[ob + 2] = o2;
    }
}

extern "C" void kernel_launch(void* const* d_in, const int* in_sizes, int n_in,
                              void* d_out, int out_size) {
    const float* node_attr = (const float*)d_in[0];
    const float* meshp     = (const float*)d_in[1];
    const float* pivp      = (const float*)d_in[2];
    const float* gamma     = (const float*)d_in[3];
    const float* beta      = (const float*)d_in[4];
    const float* Wf        = (const float*)d_in[5];
    const float* bf        = (const float*)d_in[6];
    const float* Wp        = (const float*)d_in[7];
    const float* bpv       = (const float*)d_in[8];
    const float* Wio       = (const float*)d_in[9];
    const float* bio       = (const float*)d_in[10];
    float* out = (float*)d_out;

    size_t sm3 = (size_t)(256 * 64 + 768) * 4;           // 68608 B
    size_t sm4 = (size_t)(256 * 97) * 4 + 256 * 8;       // 101376 B
    cudaFuncSetAttribute(k3, cudaFuncAttributeMaxDynamicSharedMemorySize, (int)sm3);
    cudaFuncSetAttribute(k4, cudaFuncAttributeMaxDynamicSharedMemorySize, (int)sm4);

    k1a<<<NPART, 256>>>((const float2*)meshp, (const float2*)pivp);
    k1b<<<NPIV, 128>>>();
    k2a<<<BATCH * NPIV, 64>>>(node_attr, pivp, gamma, beta, Wf, bf, Wp, bpv);
    k2b<<<dim3(128, 2), 256>>>(Wio, bio);
    k3<<<256, 128, sm3>>>();
    k4<<<NMESH / 256, 256, sm4>>>((const float2*)meshp, (const float2*)pivp, out);
}